// round 3
// baseline (speedup 1.0000x reference)
#include <cuda_runtime.h>

#define TT 4
#define BB 32
#define CC 384
#define NP 196
#define HH 8
#define HD 48
#define LB (TT*BB)     // 128 (t,b) batches
#define KD 384
#define M1 1152        // stacked q,k,v output channels

// ---------------- scratch (static device globals; no allocs) ----------------
__device__ float    g_wqkv[M1*KD];                 // folded scale*W for q,k,v stacked
__device__ float    g_bqkv[M1];
__device__ float    g_wp[CC*KD];                   // folded proj weight
__device__ float    g_bp[CC];
__device__ float    g_y1[(size_t)LB*M1*NP];        // pre-LIF qkv activations (115.6 MB)
__device__ unsigned g_s1[3*TT*BB*CC*8];            // packed spike bits: [s][t][b][c][8 words]
__device__ float    g_s2[(size_t)LB*CC*NP];        // attn-LIF spikes as 0/1 floats (38.5 MB)
__device__ float    g_y3[(size_t)LB*CC*NP];        // pre-LIF proj activations

// ---------------- weight folding: W' = scale[:,None] * W ----------------
__global__ void prep_kernel(const float* __restrict__ wq, const float* __restrict__ sq, const float* __restrict__ bq,
                            const float* __restrict__ wk, const float* __restrict__ sk, const float* __restrict__ bk,
                            const float* __restrict__ wv, const float* __restrict__ sv, const float* __restrict__ bv,
                            const float* __restrict__ wp, const float* __restrict__ sp, const float* __restrict__ bp)
{
    int idx = blockIdx.x * blockDim.x + threadIdx.x;
    if (idx < M1*KD) {
        int co = idx / KD, c = idx - co*KD;
        int s  = co / CC,  cp = co - s*CC;
        const float* w  = (s==0) ? wq : (s==1 ? wk : wv);
        const float* sc = (s==0) ? sq : (s==1 ? sk : sv);
        g_wqkv[idx] = w[cp*KD + c] * sc[cp];
        if (c == 0) {
            const float* bi = (s==0) ? bq : (s==1 ? bk : bv);
            g_bqkv[co] = bi[cp];
        }
    } else {
        int j = idx - M1*KD;
        if (j < CC*KD) {
            int cp = j / KD, c = j - cp*KD;
            g_wp[j] = wp[j] * sp[cp];
            if (c == 0) g_bp[cp] = bp[cp];
        }
    }
}

// ---------------- batched GEMM: C[l] = A @ B[l] + bias  (K=384, N=196) ----------------
// stage 0: A=g_wqkv [1152x384], B=x (ext), C=g_y1,  M=1152
// stage 1: A=g_wp   [ 384x384], B=g_s2,   C=g_y3,  M=384
// Tiles: 64x64, 256 threads, 4x4 micro-tile, K-tile 16.
__global__ void __launch_bounds__(256) gemm_kernel(const float* __restrict__ Bext, int stage)
{
    const float* __restrict__ A   = stage ? g_wp  : g_wqkv;
    const float* __restrict__ bia = stage ? g_bp  : g_bqkv;
    const float* __restrict__ Bb  = stage ? g_s2  : Bext;
    float*       __restrict__ Cb  = stage ? g_y3  : g_y1;
    const int M = stage ? CC : M1;

    const int l  = blockIdx.z;
    const int m0 = blockIdx.y * 64;
    const int n0 = blockIdx.x * 64;
    const float* __restrict__ B = Bb + (size_t)l * KD * NP;
    float*       __restrict__ Cc = Cb + (size_t)l * M * NP;

    __shared__ float As[64][17];   // [m][k] padded
    __shared__ float Bs[16][68];   // [k][n] padded

    const int tid = threadIdx.x;
    const int tx = tid & 15, ty = tid >> 4;

    // A load mapping: each thread loads a float4 along K
    const int am  = tid >> 2;       // 0..63 row within tile
    const int akq = tid & 3;        // quad of k
    // B load mapping: each thread loads a float4 along N
    const int bk  = tid >> 4;       // 0..15 k-row within tile
    const int bnq = tid & 15;       // quad of n
    const bool bvalid = (n0 + bnq*4) < NP;   // 196 % 4 == 0 -> all-or-nothing quads

    const float* Aptr = A + (size_t)(m0 + am) * KD + akq*4;
    const float* Bptr = B + (size_t)bk * NP + n0 + bnq*4;

    float acc[4][4] = {};

    for (int k0 = 0; k0 < KD; k0 += 16) {
        float4 av = *(const float4*)(Aptr + k0);
        float4 bv = bvalid ? *(const float4*)(Bptr + (size_t)k0 * NP)
                           : make_float4(0.f, 0.f, 0.f, 0.f);
        __syncthreads();
        As[am][akq*4+0] = av.x;
        As[am][akq*4+1] = av.y;
        As[am][akq*4+2] = av.z;
        As[am][akq*4+3] = av.w;
        *(float4*)&Bs[bk][bnq*4] = bv;
        __syncthreads();
#pragma unroll
        for (int kk = 0; kk < 16; kk++) {
            float4 b4 = *(const float4*)&Bs[kk][tx*4];
            float a0 = As[ty*4+0][kk];
            float a1 = As[ty*4+1][kk];
            float a2 = As[ty*4+2][kk];
            float a3 = As[ty*4+3][kk];
            acc[0][0] += a0*b4.x; acc[0][1] += a0*b4.y; acc[0][2] += a0*b4.z; acc[0][3] += a0*b4.w;
            acc[1][0] += a1*b4.x; acc[1][1] += a1*b4.y; acc[1][2] += a1*b4.z; acc[1][3] += a1*b4.w;
            acc[2][0] += a2*b4.x; acc[2][1] += a2*b4.y; acc[2][2] += a2*b4.z; acc[2][3] += a2*b4.w;
            acc[3][0] += a3*b4.x; acc[3][1] += a3*b4.y; acc[3][2] += a3*b4.z; acc[3][3] += a3*b4.w;
        }
    }

#pragma unroll
    for (int i = 0; i < 4; i++) {
        int m = m0 + ty*4 + i;
        float bi = bia[m];
#pragma unroll
        for (int j = 0; j < 4; j++) {
            int n = n0 + tx*4 + j;
            if (n < NP) Cc[(size_t)m * NP + n] = acc[i][j] + bi;
        }
    }
}

// ---------------- LIF over T for qkv + pack spikes to bits ----------------
// one block per (s, b, c) row; 224 threads = 7 warps over n (196 valid)
__global__ void __launch_bounds__(224) lif1_kernel()
{
    const int r = blockIdx.x;                 // 0 .. 3*32*384-1
    const int s = r / (BB*CC);
    const int rem = r - s*BB*CC;
    const int b = rem / CC;
    const int c = rem - b*CC;

    const int n = threadIdx.x;
    const int w = n >> 5, lane = n & 31;
    const bool valid = (n < NP);

    const size_t tstride = (size_t)BB * M1 * NP;   // 7,225,344
    const float* ybase = g_y1 + ((size_t)b*M1 + s*CC + c) * NP + n;

    float v = 0.f;
#pragma unroll
    for (int t = 0; t < TT; t++) {
        float y = valid ? ybase[(size_t)t * tstride] : 0.f;
        v += (y - v) * 0.5f;
        int sp = valid && (v >= 1.f);
        unsigned m = __ballot_sync(0xffffffffu, sp);
        unsigned base = (((unsigned)(s*TT + t) * BB + b) * CC + c) * 8u;
        if (lane == 0) g_s1[base + w] = m;
        if (n == 0)    g_s1[base + 7] = 0u;     // pad word
        if (sp) v = 0.f;
    }
}

// ---------------- attention: out = Q (K^T V) * 0.125, fused attn-LIF(0.5) ----------------
// one block per (b, head); thread = pixel n; KV[48][48] via popcount of 196-bit AND.
__global__ void __launch_bounds__(224) attn_kernel()
{
    const int bh = blockIdx.x;
    const int b = bh >> 3;
    const int h = bh & 7;

    __shared__ unsigned qb[HD][8], kb[HD][8], vb[HD][8];
    __shared__ float KVf[HD][HD];

    const int tid = threadIdx.x;
    const int n = tid;
    const bool valid = (n < NP);
    const int wq_ = n >> 5, sh = n & 31;

    float vstate[HD];
#pragma unroll
    for (int j = 0; j < HD; j++) vstate[j] = 0.f;

    for (int t = 0; t < TT; t++) {
        // load packed spike rows for this head (q, k, v): 3 * 48 * 8 words
        for (int i = tid; i < 3*CC; i += 224) {
            int s = i / CC;
            int rr = i - s*CC;
            int dd = rr >> 3, w = rr & 7;
            unsigned val = g_s1[(((unsigned)(s*TT + t) * BB + b) * CC + h*HD + dd) * 8u + w];
            unsigned (*dst)[8] = (s == 0) ? qb : (s == 1 ? kb : vb);
            dst[dd][w] = val;
        }
        __syncthreads();

        // KV[dd][d2] = popcount over pixels of k_row & v_row  (exact integer)
        for (int p = tid; p < HD*HD; p += 224) {
            int dd = p / HD, d2 = p - dd*HD;
            int cnt = 0;
#pragma unroll
            for (int w = 0; w < 7; w++) cnt += __popc(kb[dd][w] & vb[d2][w]);
            KVf[dd][d2] = (float)cnt;
        }
        __syncthreads();

        if (valid) {
            float acc[HD];
#pragma unroll
            for (int j = 0; j < HD; j++) acc[j] = 0.f;

            for (int dd = 0; dd < HD; dd++) {
                float bf = (float)((qb[dd][wq_] >> sh) & 1u);
#pragma unroll
                for (int j = 0; j < HD; j++) acc[j] += bf * KVf[dd][j];
            }

            // attn-LIF: v_th = 0.5, write 0/1 float spikes to g_s2 in [C][N] layout
            float* s2 = g_s2 + (((size_t)t*BB + b) * CC + h*HD) * NP + n;
#pragma unroll
            for (int j = 0; j < HD; j++) {
                float y = acc[j] * 0.125f;
                float v = vstate[j];
                v += (y - v) * 0.5f;
                bool sp = (v >= 0.5f);
                s2[(size_t)j * NP] = sp ? 1.f : 0.f;
                vstate[j] = sp ? 0.f : v;
            }
        }
        __syncthreads();
    }
}

// ---------------- final LIF over T -> output spikes ----------------
__global__ void lif2_kernel(float* __restrict__ out)
{
    const int S = BB*CC*NP;   // 2,408,448
    int idx = blockIdx.x * blockDim.x + threadIdx.x;
    if (idx >= S) return;
    float v = 0.f;
#pragma unroll
    for (int t = 0; t < TT; t++) {
        float y = g_y3[(size_t)t * S + idx];
        v += (y - v) * 0.5f;
        if (v >= 1.f) { out[(size_t)t * S + idx] = 1.f; v = 0.f; }
        else          { out[(size_t)t * S + idx] = 0.f; }
    }
}

// ---------------- launch ----------------
extern "C" void kernel_launch(void* const* d_in, const int* in_sizes, int n_in,
                              void* d_out, int out_size)
{
    const float* x  = (const float*)d_in[0];
    const float* wq = (const float*)d_in[1];
    const float* sq = (const float*)d_in[2];
    const float* bq = (const float*)d_in[3];
    const float* wk = (const float*)d_in[4];
    const float* sk = (const float*)d_in[5];
    const float* bk = (const float*)d_in[6];
    const float* wv = (const float*)d_in[7];
    const float* sv = (const float*)d_in[8];
    const float* bv = (const float*)d_in[9];
    const float* wp = (const float*)d_in[10];
    const float* sp = (const float*)d_in[11];
    const float* bp = (const float*)d_in[12];
    float* out = (float*)d_out;

    int prep_total = M1*KD + CC*KD;
    prep_kernel<<<(prep_total + 255)/256, 256>>>(wq,sq,bq, wk,sk,bk, wv,sv,bv, wp,sp,bp);

    // QKV GEMM: 1152x196 per (t,b)
    gemm_kernel<<<dim3(4, M1/64, LB), 256>>>(x, 0);

    // LIF over T + bit packing
    lif1_kernel<<<3*BB*CC, 224>>>();

    // attention + attn-LIF
    attn_kernel<<<BB*HH, 224>>>();

    // projection GEMM: 384x196 per (t,b)
    gemm_kernel<<<dim3(4, CC/64, LB), 256>>>(nullptr, 1);

    // final LIF -> output
    lif2_kernel<<<(BB*CC*NP + 255)/256, 256>>>(out);
}